// round 3
// baseline (speedup 1.0000x reference)
#include <cuda_runtime.h>
#include <cuda_bf16.h>
#include <cstdint>

// ---------------------------------------------------------------------------
// LJ 12-6 over a neighbor list. Round 3.
// Model: pair kernel is L1tex-wavefront-bound (~1 wf/cyc/SM).
//   - 25.6M random float4 gathers = 25.6M wavefronts (irreducible floor ~86us)
//   - idx streams (3.2M wavefronts) moved OFF L1tex via cp.async.bulk -> SMEM
//   - g_acc zeroing folded into writeout (device globals are zero-init, and
//     every replay re-zeros at the end) -> pack kernel does half the work
// ---------------------------------------------------------------------------

#define MAX_ATOMS   200000
#define TILE_PAIRS  2048
#define THREADS     256

__device__ float4 g_acc[MAX_ATOMS];   // {E, fx, fy, fz}; zero at load + after each replay
__device__ float4 g_R4[MAX_ATOMS];    // packed positions

__device__ __forceinline__ uint32_t smem_u32(const void* p) {
    return (uint32_t)__cvta_generic_to_shared(p);
}

// Kernel 1: pack R (AoS f32x3) into float4. 1 atom/thread (782 blocks, 1 wave).
__global__ void pack_kernel(const float* __restrict__ R, int n_atoms) {
    int a = blockIdx.x * blockDim.x + threadIdx.x;
    if (a < n_atoms) {
        g_R4[a] = make_float4(__ldg(&R[3 * a + 0]),
                              __ldg(&R[3 * a + 1]),
                              __ldg(&R[3 * a + 2]), 0.0f);
    }
}

// Kernel 2: pair loop. One tile of 2048 pairs per block.
// idx tiles arrive via cp.async.bulk (TMA path, no L1tex wavefronts);
// position gathers are the only L1tex consumers.
__global__ __launch_bounds__(THREADS) void lj_pairs_kernel(
        const int* __restrict__ idx_i,
        const int* __restrict__ idx_j,
        const float* __restrict__ p_eps,
        const float* __restrict__ p_sig,
        const float* __restrict__ p_cut,
        int n_pairs) {
    __shared__ __align__(16) int s_i[TILE_PAIRS];
    __shared__ __align__(16) int s_j[TILE_PAIRS];
    __shared__ __align__(8)  unsigned long long s_mbar;

    const float eps  = __ldg(p_eps);
    const float sig  = __ldg(p_sig);
    const float cut2 = __ldg(p_cut) * __ldg(p_cut);
    const float sig2 = sig * sig;

    const long long base = (long long)blockIdx.x * TILE_PAIRS;
    const int remaining  = (int)min((long long)TILE_PAIRS, (long long)n_pairs - base);
    const int bytes      = (remaining * 4 + 15) & ~15;   // 16B multiple for bulk copy

    const uint32_t mb = smem_u32(&s_mbar);
    if (threadIdx.x == 0) {
        asm volatile("mbarrier.init.shared.b64 [%0], 1;" :: "r"(mb) : "memory");
    }
    __syncthreads();
    if (threadIdx.x == 0) {
        asm volatile("mbarrier.arrive.expect_tx.shared.b64 _, [%0], %1;"
                     :: "r"(mb), "r"(2 * bytes) : "memory");
        asm volatile("cp.async.bulk.shared::cta.global.mbarrier::complete_tx::bytes "
                     "[%0], [%1], %2, [%3];"
                     :: "r"(smem_u32(s_i)), "l"(idx_i + base), "r"(bytes), "r"(mb)
                     : "memory");
        asm volatile("cp.async.bulk.shared::cta.global.mbarrier::complete_tx::bytes "
                     "[%0], [%1], %2, [%3];"
                     :: "r"(smem_u32(s_j)), "l"(idx_j + base), "r"(bytes), "r"(mb)
                     : "memory");
    }
    // Wait for both bulk copies (phase 0).
    asm volatile(
        "{\n\t"
        ".reg .pred P;\n\t"
        "LJW_%=:\n\t"
        "mbarrier.try_wait.parity.acquire.cta.shared::cta.b64 P, [%0], 0, 10000000;\n\t"
        "@!P bra LJW_%=;\n\t"
        "}" :: "r"(mb) : "memory");

    const int t = threadIdx.x;
    // Thread t, chunk c handles pairs [c*1024 + t*4, +4): int4 LDS, conflict-free.
    #pragma unroll
    for (int c = 0; c < 2; c++) {
        int p0 = c * (TILE_PAIRS / 2) + t * 4;
        if (p0 >= remaining) continue;

        int4 vi = *reinterpret_cast<const int4*>(&s_i[p0]);
        int4 vj = *reinterpret_cast<const int4*>(&s_j[p0]);
        int ii[4] = {vi.x, vi.y, vi.z, vi.w};
        int jj[4] = {vj.x, vj.y, vj.z, vj.w};
        bool ok4 = (p0 + 3 < remaining);

        float dx[4], dy[4], dz[4], r2[4];
        #pragma unroll
        for (int k = 0; k < 4; k++) {
            int i = (ok4 || p0 + k < remaining) ? ii[k] : 0;
            int j = (ok4 || p0 + k < remaining) ? jj[k] : 0;
            float4 Ri = __ldg(&g_R4[i]);
            float4 Rj = __ldg(&g_R4[j]);
            dx[k] = Ri.x - Rj.x;
            dy[k] = Ri.y - Rj.y;
            dz[k] = Ri.z - Rj.z;
            r2[k] = fmaf(dx[k], dx[k], fmaf(dy[k], dy[k], dz[k] * dz[k]));
        }

        #pragma unroll
        for (int k = 0; k < 4; k++) {
            bool live = ok4 || (p0 + k < remaining);
            if (live && r2[k] < cut2 && r2[k] > 1e-10f) {
                float inv  = __fdividef(1.0f, r2[k]);
                float sr2  = sig2 * inv;
                float sr6  = sr2 * sr2 * sr2;
                float sr12 = sr6 * sr6;
                float e    = 4.0f * eps * (sr12 - sr6);
                float fm   = 24.0f * eps * fmaf(2.0f, sr12, -sr6) * inv;
                float* acc = reinterpret_cast<float*>(&g_acc[ii[k]]);
                atomicAdd(acc + 0, e);
                atomicAdd(acc + 1, fm * dx[k]);
                atomicAdd(acc + 2, fm * dy[k]);
                atomicAdd(acc + 3, fm * dz[k]);
            }
        }
    }
}

// Kernel 3: reshape accumulators into output AND re-zero them for the next
// replay (so pack doesn't have to). 4 atoms/thread, 128-bit ld/st.
__global__ void writeout_kernel(float* __restrict__ out, int n_atoms) {
    int t = blockIdx.x * blockDim.x + threadIdx.x;
    int a = t * 4;
    float4 z = make_float4(0.0f, 0.0f, 0.0f, 0.0f);
    if (a + 3 < n_atoms) {
        float4 v0 = g_acc[a + 0];
        float4 v1 = g_acc[a + 1];
        float4 v2 = g_acc[a + 2];
        float4 v3 = g_acc[a + 3];
        g_acc[a + 0] = z; g_acc[a + 1] = z; g_acc[a + 2] = z; g_acc[a + 3] = z;
        reinterpret_cast<float4*>(out)[t] =
            make_float4(0.5f * v0.x, 0.5f * v1.x, 0.5f * v2.x, 0.5f * v3.x);
        float4* f = reinterpret_cast<float4*>(out + n_atoms) + t * 3;
        f[0] = make_float4(v0.y, v0.z, v0.w, v1.y);
        f[1] = make_float4(v1.z, v1.w, v2.y, v2.z);
        f[2] = make_float4(v2.w, v3.y, v3.z, v3.w);
    } else {
        for (int k = 0; k < 4; k++) {
            int aa = a + k;
            if (aa < n_atoms) {
                float4 v = g_acc[aa];
                g_acc[aa] = z;
                out[aa] = 0.5f * v.x;
                float* f = out + n_atoms;
                f[3 * aa + 0] = v.y;
                f[3 * aa + 1] = v.z;
                f[3 * aa + 2] = v.w;
            }
        }
    }
}

extern "C" void kernel_launch(void* const* d_in, const int* in_sizes, int n_in,
                              void* d_out, int out_size) {
    const float* R     = (const float*)d_in[0];
    const float* eps   = (const float*)d_in[1];
    const float* sig   = (const float*)d_in[2];
    const float* cut   = (const float*)d_in[3];
    const int*   idx_i = (const int*)d_in[4];
    const int*   idx_j = (const int*)d_in[5];
    float*       out   = (float*)d_out;

    int n_atoms = in_sizes[0] / 3;
    int n_pairs = in_sizes[4];

    int blocks_pack  = (n_atoms + THREADS - 1) / THREADS;
    int blocks_pairs = (int)(((long long)n_pairs + TILE_PAIRS - 1) / TILE_PAIRS);
    int atom_groups  = (n_atoms + 3) / 4;
    int blocks_wout  = (atom_groups + THREADS - 1) / THREADS;

    pack_kernel<<<blocks_pack, THREADS>>>(R, n_atoms);
    lj_pairs_kernel<<<blocks_pairs, THREADS>>>(idx_i, idx_j, eps, sig, cut, n_pairs);
    writeout_kernel<<<blocks_wout, THREADS>>>(out, n_atoms);
}

// round 4
// speedup vs baseline: 1.0993x; 1.0993x over previous
#include <cuda_runtime.h>
#include <cuda_bf16.h>

// ---------------------------------------------------------------------------
// LJ 12-6 over a neighbor list. Round 4: minimum-overhead 2-kernel structure.
//
// HW model (validated over R1-R3): the pair kernel is bound by the L1tex
// wavefront rate (~1 wf/cyc/SM). 25.6M random float4 gathers = 25.6M
// wavefronts = ~93us at NAT clock across 148 SMs. R1's pair kernel already
// sits at this floor; all remaining recoverable time is launch overhead and
// the g_acc round trip. So:
//   Kernel A: pack R (AoS f32x3 -> float4) + zero d_out (800k f32, one
//             float4 store per thread).
//   Kernel B: pair loop (R1 fast path), atomics go DIRECTLY into d_out:
//             energy (0.5 folded into the coefficient) at out[i],
//             forces at out[n_atoms + 3*i + {0,1,2}].
// Only ~2% of pairs pass the cutoff -> ~1M REDG total, negligible.
// ---------------------------------------------------------------------------

#define MAX_ATOMS 200000
#define THREADS   256

__device__ float4 g_R4[MAX_ATOMS];    // packed positions, w unused

// Kernel A: pack positions + zero the output buffer.
// out_size == 4 * n_atoms (energy[N] ++ forces[N*3]), so thread a zeroes
// float4 #a of d_out and packs atom a. One wave, minimal regs.
__global__ void pack_zero_out_kernel(const float* __restrict__ R,
                                     float4* __restrict__ out4,
                                     int n_atoms) {
    int a = blockIdx.x * blockDim.x + threadIdx.x;
    if (a < n_atoms) {
        g_R4[a] = make_float4(__ldg(&R[3 * a + 0]),
                              __ldg(&R[3 * a + 1]),
                              __ldg(&R[3 * a + 2]), 0.0f);
        out4[a] = make_float4(0.0f, 0.0f, 0.0f, 0.0f);
    }
}

// Kernel B: pair loop, 4 pairs/thread (R1-proven shape), atomics into d_out.
__global__ void lj_pairs_kernel(const int* __restrict__ idx_i,
                                const int* __restrict__ idx_j,
                                const float* __restrict__ p_eps,
                                const float* __restrict__ p_sig,
                                const float* __restrict__ p_cut,
                                float* __restrict__ out,
                                int n_atoms,
                                int n_pairs) {
    const float eps  = __ldg(p_eps);
    const float sig  = __ldg(p_sig);
    const float cut2 = __ldg(p_cut) * __ldg(p_cut);
    const float sig2 = sig * sig;

    int t    = blockIdx.x * blockDim.x + threadIdx.x;
    int base = t * 4;
    if (base >= n_pairs) return;

    float* __restrict__ fout = out + n_atoms;

    if (base + 3 < n_pairs) {
        // ---- fast path: batched loads, then sparse atomic phase ----
        int4 vi = __ldg(reinterpret_cast<const int4*>(idx_i) + t);
        int4 vj = __ldg(reinterpret_cast<const int4*>(idx_j) + t);
        int ii[4] = {vi.x, vi.y, vi.z, vi.w};
        int jj[4] = {vj.x, vj.y, vj.z, vj.w};

        float dx[4], dy[4], dz[4], r2[4];
        #pragma unroll
        for (int k = 0; k < 4; k++) {
            float4 Ri = __ldg(&g_R4[ii[k]]);
            float4 Rj = __ldg(&g_R4[jj[k]]);
            dx[k] = Ri.x - Rj.x;
            dy[k] = Ri.y - Rj.y;
            dz[k] = Ri.z - Rj.z;
            r2[k] = fmaf(dx[k], dx[k], fmaf(dy[k], dy[k], dz[k] * dz[k]));
        }

        #pragma unroll
        for (int k = 0; k < 4; k++) {
            if (r2[k] < cut2 && r2[k] > 1e-10f) {
                float inv  = __fdividef(1.0f, r2[k]);
                float sr2  = sig2 * inv;
                float sr6  = sr2 * sr2 * sr2;
                float sr12 = sr6 * sr6;
                float e    = 2.0f * eps * (sr12 - sr6);        // 0.5 * 4eps folded
                float fm   = 24.0f * eps * fmaf(2.0f, sr12, -sr6) * inv;
                int i = ii[k];
                atomicAdd(out  + i,         e);
                atomicAdd(fout + 3 * i + 0, fm * dx[k]);
                atomicAdd(fout + 3 * i + 1, fm * dy[k]);
                atomicAdd(fout + 3 * i + 2, fm * dz[k]);
            }
        }
    } else {
        // ---- tail path ----
        for (int k = 0; k < 4; k++) {
            int p = base + k;
            if (p >= n_pairs) break;
            int i = __ldg(&idx_i[p]);
            int j = __ldg(&idx_j[p]);
            float4 Ri = __ldg(&g_R4[i]);
            float4 Rj = __ldg(&g_R4[j]);
            float ddx = Ri.x - Rj.x, ddy = Ri.y - Rj.y, ddz = Ri.z - Rj.z;
            float rr2 = fmaf(ddx, ddx, fmaf(ddy, ddy, ddz * ddz));
            if (rr2 < cut2 && rr2 > 1e-10f) {
                float inv  = __fdividef(1.0f, rr2);
                float sr2  = sig2 * inv;
                float sr6  = sr2 * sr2 * sr2;
                float sr12 = sr6 * sr6;
                float e    = 2.0f * eps * (sr12 - sr6);
                float fm   = 24.0f * eps * fmaf(2.0f, sr12, -sr6) * inv;
                atomicAdd(out  + i,         e);
                atomicAdd(fout + 3 * i + 0, fm * ddx);
                atomicAdd(fout + 3 * i + 1, fm * ddy);
                atomicAdd(fout + 3 * i + 2, fm * ddz);
            }
        }
    }
}

extern "C" void kernel_launch(void* const* d_in, const int* in_sizes, int n_in,
                              void* d_out, int out_size) {
    const float* R     = (const float*)d_in[0];
    const float* eps   = (const float*)d_in[1];
    const float* sig   = (const float*)d_in[2];
    const float* cut   = (const float*)d_in[3];
    const int*   idx_i = (const int*)d_in[4];
    const int*   idx_j = (const int*)d_in[5];
    float*       out   = (float*)d_out;

    int n_atoms = in_sizes[0] / 3;
    int n_pairs = in_sizes[4];

    int blocks_atoms = (n_atoms + THREADS - 1) / THREADS;
    int n_groups     = (n_pairs + 3) / 4;
    int blocks_pairs = (n_groups + THREADS - 1) / THREADS;

    pack_zero_out_kernel<<<blocks_atoms, THREADS>>>(
        R, reinterpret_cast<float4*>(out), n_atoms);
    lj_pairs_kernel<<<blocks_pairs, THREADS>>>(
        idx_i, idx_j, eps, sig, cut, out, n_atoms, n_pairs);
}